// round 3
// baseline (speedup 1.0000x reference)
#include <cuda_runtime.h>
#include <math.h>

#define NN 33
#define TT 1024
#define EE 97
#define H1 8
#define HC 512
#define C2 512
#define HID1 128
#define Z1 512
#define NC2 16896
#define HID2 64
#define Z2 256
#define WREG 64
#define WSM  64   // columns streamed from smem (WREG + WSM == HID1)

__device__ float d_ep1[EE * HC];
__device__ float d_ep2[EE * C2];
__device__ int   d_csr_start[NN + 1];
__device__ int   d_csr_eid[EE];
__device__ int   d_src[EE];
__device__ int   d_dst[EE];
__device__ float d_h1[TT * NN * HC];
__device__ float d_hl[TT * NN * C2];
__device__ float d_hr[TT * NN * C2];
__device__ float d_seq[NN * TT * C2];
__device__ float d_xpre1[TT * Z1];
__device__ float d_hs1[TT * HID1];
__device__ float d_xpre2[TT * Z2];
__device__ float d_lb1[Z1];
__device__ float d_lb2[Z2];

__device__ __forceinline__ float sigm(float x) { return 1.0f / (1.0f + expf(-x)); }

// ---------- K0: setup ----------
__global__ __launch_bounds__(512) void k_setup(const int* __restrict__ ei, const float* __restrict__ ea,
                        const float* __restrict__ g1_we, const float* __restrict__ g2_we,
                        const float* __restrict__ b1i, const float* __restrict__ b1h,
                        const float* __restrict__ b2i, const float* __restrict__ b2h) {
    __shared__ int cnt[NN + 1];
    __shared__ int pos[NN];
    int tid = threadIdx.x;
    if (tid == 0) {
        for (int n = 0; n <= NN; n++) cnt[n] = 0;
        for (int e = 0; e < EE; e++) {
            d_src[e] = ei[e];
            d_dst[e] = ei[EE + e];
            cnt[ei[EE + e] + 1]++;
        }
        for (int n = 0; n < NN; n++) cnt[n + 1] += cnt[n];
        for (int n = 0; n <= NN; n++) d_csr_start[n] = cnt[n];
        for (int n = 0; n < NN; n++) pos[n] = cnt[n];
        for (int e = 0; e < EE; e++) d_csr_eid[pos[ei[EE + e]]++] = e;
    }
    for (int e = 0; e < EE; e++) {
        float a0 = ea[e * 3], a1 = ea[e * 3 + 1], a2 = ea[e * 3 + 2];
        d_ep1[e * HC + tid] = a0 * g1_we[tid] + a1 * g1_we[HC + tid] + a2 * g1_we[2 * HC + tid];
        d_ep2[e * C2 + tid] = a0 * g2_we[tid] + a1 * g2_we[C2 + tid] + a2 * g2_we[2 * C2 + tid];
    }
    d_lb1[tid] = b1i[tid] + b1h[tid];
    if (tid < Z2) d_lb2[tid] = b2i[tid] + b2h[tid];
}

// ---------- K1: GAT1 (one block per t) ----------
__global__ __launch_bounds__(512) void k_gat1(const float* __restrict__ x,
                                              const float* __restrict__ wl,
                                              const float* __restrict__ wr,
                                              const float* __restrict__ att,
                                              const float* __restrict__ bias) {
    int t = blockIdx.x;
    int tid = threadIdx.x;
    extern __shared__ float sm[];
    float* xl    = sm;            // 16896
    float* part  = xl + 16896;    // 97*16
    float* logit = part + 1552;   // 97*8
    float* alpha = logit + 776;   // 97*8
    float* sx    = alpha + 776;   // 68
    int* cstart = (int*)(sx + 68);
    int* ceid   = cstart + NN + 1;
    int* csrc   = ceid + EE;
    int* cdst   = csrc + EE;

    if (tid < 2 * NN) sx[tid] = x[t * (2 * NN) + tid];
    if (tid < NN + 1) cstart[tid] = d_csr_start[tid];
    if (tid < EE) { ceid[tid] = d_csr_eid[tid]; csrc[tid] = d_src[tid]; cdst[tid] = d_dst[tid]; }
    float wl0 = wl[tid], wl1 = wl[HC + tid];
    float wr0 = wr[tid], wr1 = wr[HC + tid];
    float attc = att[tid];
    __syncthreads();

    for (int n = 0; n < NN; n++)
        xl[n * HC + tid] = fmaf(sx[2 * n], wl0, sx[2 * n + 1] * wl1);
    __syncthreads();

    int lane = tid & 31, warp = tid >> 5;
#pragma unroll 4
    for (int e = 0; e < EE; e++) {
        int s = csrc[e], d = cdst[e];
        float xr = fmaf(sx[2 * d], wr0, sx[2 * d + 1] * wr1);
        float v = xl[s * HC + tid] + xr + d_ep1[e * HC + tid];
        v = fmaxf(v, 0.2f * v);
        v *= attc;
        v += __shfl_xor_sync(0xffffffffu, v, 16);
        v += __shfl_xor_sync(0xffffffffu, v, 8);
        v += __shfl_xor_sync(0xffffffffu, v, 4);
        v += __shfl_xor_sync(0xffffffffu, v, 2);
        v += __shfl_xor_sync(0xffffffffu, v, 1);
        if (lane == 0) part[e * 16 + warp] = v;
    }
    __syncthreads();
    for (int idx = tid; idx < EE * H1; idx += 512) {
        int e = idx >> 3, h = idx & 7;
        logit[idx] = part[e * 16 + 2 * h] + part[e * 16 + 2 * h + 1];
    }
    __syncthreads();
    for (int idx = tid; idx < NN * H1; idx += 512) {
        int n = idx >> 3, h = idx & 7;
        int s0 = cstart[n], s1 = cstart[n + 1];
        float m = -INFINITY;
        for (int p = s0; p < s1; p++) m = fmaxf(m, logit[ceid[p] * 8 + h]);
        float den = 0.0f;
        for (int p = s0; p < s1; p++) {
            float ex = expf(logit[ceid[p] * 8 + h] - m);
            den += ex;
            alpha[ceid[p] * 8 + h] = ex;
        }
        float inv = 1.0f / (den + 1e-16f);
        for (int p = s0; p < s1; p++) alpha[ceid[p] * 8 + h] *= inv;
    }
    __syncthreads();
    int h = tid >> 6;
    float b = bias[tid];
    for (int n = 0; n < NN; n++) {
        int s0 = cstart[n], s1 = cstart[n + 1];
        float acc = 0.0f;
        for (int p = s0; p < s1; p++) {
            int e = ceid[p];
            acc = fmaf(alpha[e * 8 + h], xl[csrc[e] * HC + tid], acc);
        }
        float o = acc + b;
        o = o > 0.0f ? o : expm1f(o);
        d_h1[(t * NN + n) * HC + tid] = o;
    }
}

// ---------- K2: GEMM1  [hl|hr] = h1 @ [g2_wl|g2_wr]  M=33792 N=1024 K=512 ----------
__global__ __launch_bounds__(256) void k_gemm1(const float* __restrict__ Bwl,
                                               const float* __restrict__ Bwr) {
    int n0 = blockIdx.x * 128;
    int by = blockIdx.y;
    const float* A = d_h1;
    const float* B = (n0 < 512) ? (Bwl + n0) : (Bwr + (n0 - 512));
    float*       C = (n0 < 512) ? (d_hl + n0) : (d_hr + (n0 - 512));
    __shared__ float As[8][128];
    __shared__ float Bs[8][128];
    int tid = threadIdx.x;
    int tx = tid & 15, ty = tid >> 4;
    float acc[8][8];
#pragma unroll
    for (int i = 0; i < 8; i++)
#pragma unroll
        for (int j = 0; j < 8; j++) acc[i][j] = 0.0f;
    int arow = tid >> 1, acol = (tid & 1) * 4;
    int brow = tid >> 5, bcol = (tid & 31) * 4;
    long abase = (long)(by * 128 + arow) * 512 + acol;
    for (int k0 = 0; k0 < 512; k0 += 8) {
        float4 av = *(const float4*)(A + abase + k0);
        float4 bv = *(const float4*)(B + (k0 + brow) * 512 + bcol);
        As[acol + 0][arow] = av.x; As[acol + 1][arow] = av.y;
        As[acol + 2][arow] = av.z; As[acol + 3][arow] = av.w;
        *(float4*)&Bs[brow][bcol] = bv;
        __syncthreads();
#pragma unroll
        for (int kk = 0; kk < 8; kk++) {
            float a[8], b[8];
            *(float4*)(a)     = *(float4*)&As[kk][ty * 8];
            *(float4*)(a + 4) = *(float4*)&As[kk][ty * 8 + 4];
            *(float4*)(b)     = *(float4*)&Bs[kk][tx * 8];
            *(float4*)(b + 4) = *(float4*)&Bs[kk][tx * 8 + 4];
#pragma unroll
            for (int i = 0; i < 8; i++)
#pragma unroll
                for (int j = 0; j < 8; j++) acc[i][j] = fmaf(a[i], b[j], acc[i][j]);
        }
        __syncthreads();
    }
#pragma unroll
    for (int i = 0; i < 8; i++) {
        long m = (long)(by * 128 + ty * 8 + i) * 512 + tx * 8;
        *(float4*)(C + m)     = make_float4(acc[i][0], acc[i][1], acc[i][2], acc[i][3]);
        *(float4*)(C + m + 4) = make_float4(acc[i][4], acc[i][5], acc[i][6], acc[i][7]);
    }
}

// ---------- K3: GAT2 (one block per t) ----------
__global__ __launch_bounds__(512) void k_gat2(const float* __restrict__ att2,
                                              const float* __restrict__ bias2) {
    int t = blockIdx.x;
    int tid = threadIdx.x;
    extern __shared__ float sm[];
    float* hl    = sm;
    float* hr    = hl + 16896;
    float* part  = hr + 16896;   // 1552
    float* logit = part + 1552;  // 104
    float* alpha = logit + 104;  // 104
    int* cstart = (int*)(alpha + 104);
    int* ceid   = cstart + NN + 1;
    int* csrc   = ceid + EE;
    int* cdst   = csrc + EE;

    const float4* srcl = (const float4*)(d_hl + (long)t * NC2);
    const float4* srcr = (const float4*)(d_hr + (long)t * NC2);
    for (int i = tid; i < NC2 / 4; i += 512) {
        ((float4*)hl)[i] = srcl[i];
        ((float4*)hr)[i] = srcr[i];
    }
    if (tid < NN + 1) cstart[tid] = d_csr_start[tid];
    if (tid < EE) { ceid[tid] = d_csr_eid[tid]; csrc[tid] = d_src[tid]; cdst[tid] = d_dst[tid]; }
    float attc = att2[tid];
    float b = bias2[tid];
    __syncthreads();

    int lane = tid & 31, warp = tid >> 5;
#pragma unroll 4
    for (int e = 0; e < EE; e++) {
        int s = csrc[e], d = cdst[e];
        float v = hl[s * C2 + tid] + hr[d * C2 + tid] + d_ep2[e * C2 + tid];
        v = fmaxf(v, 0.2f * v);
        v *= attc;
        v += __shfl_xor_sync(0xffffffffu, v, 16);
        v += __shfl_xor_sync(0xffffffffu, v, 8);
        v += __shfl_xor_sync(0xffffffffu, v, 4);
        v += __shfl_xor_sync(0xffffffffu, v, 2);
        v += __shfl_xor_sync(0xffffffffu, v, 1);
        if (lane == 0) part[e * 16 + warp] = v;
    }
    __syncthreads();
    if (tid < EE) {
        float s = 0.0f;
        for (int w = 0; w < 16; w++) s += part[tid * 16 + w];
        logit[tid] = s;
    }
    __syncthreads();
    if (tid < NN) {
        int s0 = cstart[tid], s1 = cstart[tid + 1];
        float m = -INFINITY;
        for (int p = s0; p < s1; p++) m = fmaxf(m, logit[ceid[p]]);
        float den = 0.0f;
        for (int p = s0; p < s1; p++) {
            float ex = expf(logit[ceid[p]] - m);
            den += ex;
            alpha[ceid[p]] = ex;
        }
        float inv = 1.0f / (den + 1e-16f);
        for (int p = s0; p < s1; p++) alpha[ceid[p]] *= inv;
    }
    __syncthreads();
    for (int n = 0; n < NN; n++) {
        int s0 = cstart[n], s1 = cstart[n + 1];
        float acc = 0.0f;
        for (int p = s0; p < s1; p++) {
            int e = ceid[p];
            acc = fmaf(alpha[e], hl[csrc[e] * C2 + tid], acc);
        }
        float o = acc + b;
        o = o > 0.0f ? o : expm1f(o);
        d_seq[((long)n * TT + t) * C2 + tid] = o;   // scrambled reshape
    }
}

// ---------- K4a: init xpre1 with biases ----------
__global__ __launch_bounds__(512) void k_xpre_init() {
    d_xpre1[blockIdx.x * Z1 + threadIdx.x] = d_lb1[threadIdx.x];
}

// ---------- K4: split-K NT GEMM  xpre1 += seq @ l1_wih^T  (1024x512, K=16896) ----------
__global__ __launch_bounds__(256) void k_gemm2(const float* __restrict__ Bw) {
    int bx = blockIdx.x, by = blockIdx.y, bz = blockIdx.z;
    __shared__ float As[16][64];
    __shared__ float Bs[16][64];
    int tid = threadIdx.x;
    int tx = tid & 15, ty = tid >> 4;
    float acc[4][4];
#pragma unroll
    for (int i = 0; i < 4; i++)
#pragma unroll
        for (int j = 0; j < 4; j++) acc[i][j] = 0.0f;
    int lrow = tid >> 2, lc4 = (tid & 3) * 4;
    long abase = (long)(by * 64 + lrow) * NC2 + lc4;
    long bbase = (long)(bx * 64 + lrow) * NC2 + lc4;
    int k0 = 2112 * bz, kend = k0 + 2112;
    for (; k0 < kend; k0 += 16) {
        float4 av = *(const float4*)(d_seq + abase + k0);
        float4 bv = *(const float4*)(Bw + bbase + k0);
        As[lc4 + 0][lrow] = av.x; As[lc4 + 1][lrow] = av.y;
        As[lc4 + 2][lrow] = av.z; As[lc4 + 3][lrow] = av.w;
        Bs[lc4 + 0][lrow] = bv.x; Bs[lc4 + 1][lrow] = bv.y;
        Bs[lc4 + 2][lrow] = bv.z; Bs[lc4 + 3][lrow] = bv.w;
        __syncthreads();
#pragma unroll
        for (int kk = 0; kk < 16; kk++) {
            float a[4], b[4];
            *(float4*)a = *(float4*)&As[kk][ty * 4];
            *(float4*)b = *(float4*)&Bs[kk][tx * 4];
#pragma unroll
            for (int i = 0; i < 4; i++)
#pragma unroll
                for (int j = 0; j < 4; j++) acc[i][j] = fmaf(a[i], b[j], acc[i][j]);
        }
        __syncthreads();
    }
#pragma unroll
    for (int i = 0; i < 4; i++)
#pragma unroll
        for (int j = 0; j < 4; j++)
            atomicAdd(&d_xpre1[(by * 64 + ty * 4 + i) * Z1 + bx * 64 + tx * 4 + j], acc[i][j]);
}

// ---------- K5: LSTM1 recurrence (single block, 512 threads) ----------
// 64 whh columns per gate-row in registers, 64 streamed from smem [chunk][thread] float4.
__global__ __launch_bounds__(512, 1) void k_lstm1(const float* __restrict__ whh) {
    int j = threadIdx.x;
    extern __shared__ float sm[];
    float* sw  = sm;                       // WSM/4 chunks * 512 float4 = 32768 floats
    float* hsm = sw + (WSM / 4) * 512 * 4; // 128
    float* zsm = hsm + 128;                // 512
    float wreg[WREG];
#pragma unroll
    for (int k4 = 0; k4 < WREG / 4; k4++) {
        float4 v = *(const float4*)(whh + j * HID1 + k4 * 4);
        wreg[4 * k4] = v.x; wreg[4 * k4 + 1] = v.y;
        wreg[4 * k4 + 2] = v.z; wreg[4 * k4 + 3] = v.w;
    }
#pragma unroll
    for (int kk4 = 0; kk4 < WSM / 4; kk4++)
        ((float4*)sw)[kk4 * 512 + j] = *(const float4*)(whh + j * HID1 + WREG + kk4 * 4);
    if (j < HID1) hsm[j] = 0.0f;
    float c = 0.0f;
    __syncthreads();

    const float4* h4 = (const float4*)hsm;
    const float4* sw4 = (const float4*)sw;
    for (int t = 0; t < TT; t++) {
        float p0 = d_xpre1[t * Z1 + j], p1 = 0.0f, p2 = 0.0f, p3 = 0.0f;
#pragma unroll
        for (int k4 = 0; k4 < WREG / 4; k4++) {
            float4 hv = h4[k4];
            p0 = fmaf(wreg[4 * k4],     hv.x, p0);
            p1 = fmaf(wreg[4 * k4 + 1], hv.y, p1);
            p2 = fmaf(wreg[4 * k4 + 2], hv.z, p2);
            p3 = fmaf(wreg[4 * k4 + 3], hv.w, p3);
        }
#pragma unroll
        for (int kk4 = 0; kk4 < WSM / 4; kk4++) {
            float4 w = sw4[kk4 * 512 + j];
            float4 hv = h4[WREG / 4 + kk4];
            p0 = fmaf(w.x, hv.x, p0);
            p1 = fmaf(w.y, hv.y, p1);
            p2 = fmaf(w.z, hv.z, p2);
            p3 = fmaf(w.w, hv.w, p3);
        }
        zsm[j] = (p0 + p1) + (p2 + p3);
        __syncthreads();
        if (j < HID1) {
            float zi = zsm[j], zf = zsm[HID1 + j], zg = zsm[2 * HID1 + j], zo = zsm[3 * HID1 + j];
            c = sigm(zf) * c + sigm(zi) * tanhf(zg);
            float h = sigm(zo) * tanhf(c);
            hsm[j] = h;
            d_hs1[t * HID1 + j] = h;
        }
        __syncthreads();
    }
}

// ---------- K6: xpre2 = hs1 @ l2_wih^T + lb2 ----------
__global__ __launch_bounds__(256) void k_xpre2(const float* __restrict__ wih2) {
    int t = blockIdx.x;
    int tid = threadIdx.x;
    __shared__ float h[HID1];
    if (tid < HID1) h[tid] = d_hs1[t * HID1 + tid];
    __syncthreads();
    const float4* w4 = (const float4*)(wih2 + tid * HID1);
    const float4* h4 = (const float4*)h;
    float p0 = 0, p1 = 0, p2 = 0, p3 = 0;
#pragma unroll
    for (int k4 = 0; k4 < HID1 / 4; k4++) {
        float4 w = w4[k4], hv = h4[k4];
        p0 = fmaf(w.x, hv.x, p0); p1 = fmaf(w.y, hv.y, p1);
        p2 = fmaf(w.z, hv.z, p2); p3 = fmaf(w.w, hv.w, p3);
    }
    d_xpre2[t * Z2 + tid] = (p0 + p1) + (p2 + p3) + d_lb2[tid];
}

// ---------- K7: LSTM2 recurrence + FC ----------
__global__ __launch_bounds__(256, 1) void k_lstm2(const float* __restrict__ whh2,
                                                  const float* __restrict__ fcw,
                                                  const float* __restrict__ fcb,
                                                  float* __restrict__ out) {
    int j = threadIdx.x;
    __shared__ float hsm[HID2];
    __shared__ float zsm[Z2];
    float wreg[HID2];
#pragma unroll
    for (int k4 = 0; k4 < HID2 / 4; k4++) {
        float4 v = *(const float4*)(whh2 + j * HID2 + k4 * 4);
        wreg[4 * k4] = v.x; wreg[4 * k4 + 1] = v.y;
        wreg[4 * k4 + 2] = v.z; wreg[4 * k4 + 3] = v.w;
    }
    if (j < HID2) hsm[j] = 0.0f;
    float c = 0.0f;
    __syncthreads();
    const float4* h4 = (const float4*)hsm;
    for (int t = 0; t < TT; t++) {
        float p0 = d_xpre2[t * Z2 + j], p1 = 0, p2 = 0, p3 = 0;
#pragma unroll
        for (int k4 = 0; k4 < HID2 / 4; k4++) {
            float4 hv = h4[k4];
            p0 = fmaf(wreg[4 * k4],     hv.x, p0);
            p1 = fmaf(wreg[4 * k4 + 1], hv.y, p1);
            p2 = fmaf(wreg[4 * k4 + 2], hv.z, p2);
            p3 = fmaf(wreg[4 * k4 + 3], hv.w, p3);
        }
        zsm[j] = (p0 + p1) + (p2 + p3);
        __syncthreads();
        if (j < HID2) {
            float zi = zsm[j], zf = zsm[HID2 + j], zg = zsm[2 * HID2 + j], zo = zsm[3 * HID2 + j];
            c = sigm(zf) * c + sigm(zi) * tanhf(zg);
            hsm[j] = sigm(zo) * tanhf(c);
        }
        __syncthreads();
    }
    if (j < 4) {
        float acc = fcb[j];
        for (int k = 0; k < HID2; k++) acc = fmaf(fcw[j * HID2 + k], hsm[k], acc);
        out[j] = acc;
    }
}

extern "C" void kernel_launch(void* const* d_in, const int* in_sizes, int n_in,
                              void* d_out, int out_size) {
    const float* x      = (const float*)d_in[0];
    const int*   ei     = (const int*)d_in[1];
    const float* ea     = (const float*)d_in[2];
    const float* g1_wl  = (const float*)d_in[3];
    const float* g1_wr  = (const float*)d_in[4];
    const float* g1_we  = (const float*)d_in[5];
    const float* g1_att = (const float*)d_in[6];
    const float* g1_b   = (const float*)d_in[7];
    const float* g2_wl  = (const float*)d_in[8];
    const float* g2_wr  = (const float*)d_in[9];
    const float* g2_we  = (const float*)d_in[10];
    const float* g2_att = (const float*)d_in[11];
    const float* g2_b   = (const float*)d_in[12];
    const float* l1_wih = (const float*)d_in[13];
    const float* l1_whh = (const float*)d_in[14];
    const float* l1_bih = (const float*)d_in[15];
    const float* l1_bhh = (const float*)d_in[16];
    const float* l2_wih = (const float*)d_in[17];
    const float* l2_whh = (const float*)d_in[18];
    const float* l2_bih = (const float*)d_in[19];
    const float* l2_bhh = (const float*)d_in[20];
    const float* fc_w   = (const float*)d_in[21];
    const float* fc_b   = (const float*)d_in[22];
    float* out = (float*)d_out;

    const int SMEM_GAT1  = (16896 + 1552 + 776 + 776 + 68) * 4 + 325 * 4;
    const int SMEM_GAT2  = (16896 + 16896 + 1552 + 104 + 104) * 4 + 325 * 4;
    const int SMEM_LSTM1 = ((WSM / 4) * 512 * 4 + 128 + 512) * 4;
    cudaFuncSetAttribute(k_gat1, cudaFuncAttributeMaxDynamicSharedMemorySize, SMEM_GAT1);
    cudaFuncSetAttribute(k_gat2, cudaFuncAttributeMaxDynamicSharedMemorySize, SMEM_GAT2);
    cudaFuncSetAttribute(k_lstm1, cudaFuncAttributeMaxDynamicSharedMemorySize, SMEM_LSTM1);

    k_setup<<<1, 512>>>(ei, ea, g1_we, g2_we, l1_bih, l1_bhh, l2_bih, l2_bhh);
    k_gat1<<<TT, 512, SMEM_GAT1>>>(x, g1_wl, g1_wr, g1_att, g1_b);
    k_gemm1<<<dim3(8, 264), 256>>>(g2_wl, g2_wr);
    k_gat2<<<TT, 512, SMEM_GAT2>>>(g2_att, g2_b);
    k_xpre_init<<<TT, Z1>>>();
    k_gemm2<<<dim3(8, 16, 8), 256>>>(l1_wih);
    k_lstm1<<<1, 512, SMEM_LSTM1>>>(l1_whh);
    k_xpre2<<<TT, 256>>>(l2_wih);
    k_lstm2<<<1, 256>>>(l2_whh, fc_w, fc_b, out);
}

// round 4
// speedup vs baseline: 1.1087x; 1.1087x over previous
#include <cuda_runtime.h>
#include <math.h>

#define NN 33
#define TT 1024
#define EE 97
#define H1 8
#define HC 512
#define C2 512
#define HID1 128
#define Z1 512
#define NC2 16896
#define HID2 64
#define Z2 256
#define WREG 88
#define WSM  40   // WREG + WSM == HID1

typedef unsigned long long ull;

__device__ float d_ep1[EE * HC];
__device__ float d_ep2[EE * C2];
__device__ int   d_csr_start[NN + 1];
__device__ int   d_csr_eid[EE];
__device__ int   d_src[EE];
__device__ int   d_dst[EE];
__device__ float d_h1[TT * NN * HC];
__device__ float d_hl[TT * NN * C2];
__device__ float d_hr[TT * NN * C2];
__device__ float d_seq[NN * TT * C2];
__device__ float d_xpre1[TT * Z1];
__device__ float d_hs1[TT * HID1];
__device__ float d_xpre2[TT * Z2];
__device__ float d_lb1[Z1];
__device__ float d_lb2[Z2];

__device__ __forceinline__ float sigm(float x) { return 1.0f / (1.0f + expf(-x)); }

// packed fp32x2 FMA (exact fp32 per lane, 2x throughput vs FFMA)
__device__ __forceinline__ ull ffma2(ull a, ull b, ull c) {
    ull d;
    asm("fma.rn.f32x2 %0, %1, %2, %3;" : "=l"(d) : "l"(a), "l"(b), "l"(c));
    return d;
}
__device__ __forceinline__ ull pk2(float lo, float hi) {
    ull r;
    asm("mov.b64 %0, {%1, %2};" : "=l"(r) : "f"(lo), "f"(hi));
    return r;
}
__device__ __forceinline__ float2 upk2(ull v) {
    float2 f;
    asm("mov.b64 {%0, %1}, %2;" : "=f"(f.x), "=f"(f.y) : "l"(v));
    return f;
}

// ---------- K0: setup ----------
__global__ __launch_bounds__(512) void k_setup(const int* __restrict__ ei, const float* __restrict__ ea,
                        const float* __restrict__ g1_we, const float* __restrict__ g2_we,
                        const float* __restrict__ b1i, const float* __restrict__ b1h,
                        const float* __restrict__ b2i, const float* __restrict__ b2h) {
    __shared__ int cnt[NN + 1];
    __shared__ int pos[NN];
    int tid = threadIdx.x;
    if (tid == 0) {
        for (int n = 0; n <= NN; n++) cnt[n] = 0;
        for (int e = 0; e < EE; e++) {
            d_src[e] = ei[e];
            d_dst[e] = ei[EE + e];
            cnt[ei[EE + e] + 1]++;
        }
        for (int n = 0; n < NN; n++) cnt[n + 1] += cnt[n];
        for (int n = 0; n <= NN; n++) d_csr_start[n] = cnt[n];
        for (int n = 0; n < NN; n++) pos[n] = cnt[n];
        for (int e = 0; e < EE; e++) d_csr_eid[pos[ei[EE + e]]++] = e;
    }
    for (int e = 0; e < EE; e++) {
        float a0 = ea[e * 3], a1 = ea[e * 3 + 1], a2 = ea[e * 3 + 2];
        d_ep1[e * HC + tid] = a0 * g1_we[tid] + a1 * g1_we[HC + tid] + a2 * g1_we[2 * HC + tid];
        d_ep2[e * C2 + tid] = a0 * g2_we[tid] + a1 * g2_we[C2 + tid] + a2 * g2_we[2 * C2 + tid];
    }
    d_lb1[tid] = b1i[tid] + b1h[tid];
    if (tid < Z2) d_lb2[tid] = b2i[tid] + b2h[tid];
}

// ---------- K1: GAT1 (one block per t) ----------
__global__ __launch_bounds__(512) void k_gat1(const float* __restrict__ x,
                                              const float* __restrict__ wl,
                                              const float* __restrict__ wr,
                                              const float* __restrict__ att,
                                              const float* __restrict__ bias) {
    int t = blockIdx.x;
    int tid = threadIdx.x;
    extern __shared__ float sm[];
    float* xl    = sm;            // 16896
    float* part  = xl + 16896;    // 97*16
    float* logit = part + 1552;   // 97*8
    float* alpha = logit + 776;   // 97*8
    float* sx    = alpha + 776;   // 68
    int* cstart = (int*)(sx + 68);
    int* ceid   = cstart + NN + 1;
    int* csrc   = ceid + EE;
    int* cdst   = csrc + EE;

    if (tid < 2 * NN) sx[tid] = x[t * (2 * NN) + tid];
    if (tid < NN + 1) cstart[tid] = d_csr_start[tid];
    if (tid < EE) { ceid[tid] = d_csr_eid[tid]; csrc[tid] = d_src[tid]; cdst[tid] = d_dst[tid]; }
    float wl0 = wl[tid], wl1 = wl[HC + tid];
    float wr0 = wr[tid], wr1 = wr[HC + tid];
    float attc = att[tid];
    __syncthreads();

    for (int n = 0; n < NN; n++)
        xl[n * HC + tid] = fmaf(sx[2 * n], wl0, sx[2 * n + 1] * wl1);
    __syncthreads();

    int lane = tid & 31, warp = tid >> 5;
#pragma unroll 4
    for (int e = 0; e < EE; e++) {
        int s = csrc[e], d = cdst[e];
        float xr = fmaf(sx[2 * d], wr0, sx[2 * d + 1] * wr1);
        float v = xl[s * HC + tid] + xr + d_ep1[e * HC + tid];
        v = fmaxf(v, 0.2f * v);
        v *= attc;
        v += __shfl_xor_sync(0xffffffffu, v, 16);
        v += __shfl_xor_sync(0xffffffffu, v, 8);
        v += __shfl_xor_sync(0xffffffffu, v, 4);
        v += __shfl_xor_sync(0xffffffffu, v, 2);
        v += __shfl_xor_sync(0xffffffffu, v, 1);
        if (lane == 0) part[e * 16 + warp] = v;
    }
    __syncthreads();
    for (int idx = tid; idx < EE * H1; idx += 512) {
        int e = idx >> 3, h = idx & 7;
        logit[idx] = part[e * 16 + 2 * h] + part[e * 16 + 2 * h + 1];
    }
    __syncthreads();
    for (int idx = tid; idx < NN * H1; idx += 512) {
        int n = idx >> 3, h = idx & 7;
        int s0 = cstart[n], s1 = cstart[n + 1];
        float m = -INFINITY;
        for (int p = s0; p < s1; p++) m = fmaxf(m, logit[ceid[p] * 8 + h]);
        float den = 0.0f;
        for (int p = s0; p < s1; p++) {
            float ex = expf(logit[ceid[p] * 8 + h] - m);
            den += ex;
            alpha[ceid[p] * 8 + h] = ex;
        }
        float inv = 1.0f / (den + 1e-16f);
        for (int p = s0; p < s1; p++) alpha[ceid[p] * 8 + h] *= inv;
    }
    __syncthreads();
    int h = tid >> 6;
    float b = bias[tid];
    for (int n = 0; n < NN; n++) {
        int s0 = cstart[n], s1 = cstart[n + 1];
        float acc = 0.0f;
        for (int p = s0; p < s1; p++) {
            int e = ceid[p];
            acc = fmaf(alpha[e * 8 + h], xl[csrc[e] * HC + tid], acc);
        }
        float o = acc + b;
        o = o > 0.0f ? o : expm1f(o);
        d_h1[(t * NN + n) * HC + tid] = o;
    }
}

// ---------- K2: GEMM1  [hl|hr] = h1 @ [g2_wl|g2_wr]  M=33792 N=1024 K=512, FFMA2 ----------
__global__ __launch_bounds__(256) void k_gemm1(const float* __restrict__ Bwl,
                                               const float* __restrict__ Bwr) {
    int n0 = blockIdx.x * 128;
    int by = blockIdx.y;
    const float* A = d_h1;
    const float* B = (n0 < 512) ? (Bwl + n0) : (Bwr + (n0 - 512));
    float*       C = (n0 < 512) ? (d_hl + n0) : (d_hr + (n0 - 512));
    __shared__ __align__(16) float As[8][128];
    __shared__ __align__(16) float Bs[8][128];
    int tid = threadIdx.x;
    int tx = tid & 15, ty = tid >> 4;
    ull acc2[8][4];
#pragma unroll
    for (int i = 0; i < 8; i++)
#pragma unroll
        for (int j = 0; j < 4; j++) acc2[i][j] = 0ull;
    int arow = tid >> 1, acol = (tid & 1) * 4;
    int brow = tid >> 5, bcol = (tid & 31) * 4;
    long abase = (long)(by * 128 + arow) * 512 + acol;
    for (int k0 = 0; k0 < 512; k0 += 8) {
        float4 av = *(const float4*)(A + abase + k0);
        float4 bv = *(const float4*)(B + (k0 + brow) * 512 + bcol);
        As[acol + 0][arow] = av.x; As[acol + 1][arow] = av.y;
        As[acol + 2][arow] = av.z; As[acol + 3][arow] = av.w;
        *(float4*)&Bs[brow][bcol] = bv;
        __syncthreads();
#pragma unroll
        for (int kk = 0; kk < 8; kk++) {
            float a[8];
            *(float4*)(a)     = *(float4*)&As[kk][ty * 8];
            *(float4*)(a + 4) = *(float4*)&As[kk][ty * 8 + 4];
            ulonglong2 b0 = *(const ulonglong2*)&Bs[kk][tx * 8];
            ulonglong2 b1 = *(const ulonglong2*)&Bs[kk][tx * 8 + 4];
#pragma unroll
            for (int i = 0; i < 8; i++) {
                ull ap = pk2(a[i], a[i]);
                acc2[i][0] = ffma2(ap, b0.x, acc2[i][0]);
                acc2[i][1] = ffma2(ap, b0.y, acc2[i][1]);
                acc2[i][2] = ffma2(ap, b1.x, acc2[i][2]);
                acc2[i][3] = ffma2(ap, b1.y, acc2[i][3]);
            }
        }
        __syncthreads();
    }
#pragma unroll
    for (int i = 0; i < 8; i++) {
        long m = (long)(by * 128 + ty * 8 + i) * 512 + tx * 8;
        float2 f0 = upk2(acc2[i][0]), f1 = upk2(acc2[i][1]);
        float2 f2 = upk2(acc2[i][2]), f3 = upk2(acc2[i][3]);
        *(float4*)(C + m)     = make_float4(f0.x, f0.y, f1.x, f1.y);
        *(float4*)(C + m + 4) = make_float4(f2.x, f2.y, f3.x, f3.y);
    }
}

// ---------- K3: GAT2 (one block per t; hr read from global via L1) ----------
__global__ __launch_bounds__(512) void k_gat2(const float* __restrict__ att2,
                                              const float* __restrict__ bias2) {
    int t = blockIdx.x;
    int tid = threadIdx.x;
    extern __shared__ float sm[];
    float* hl    = sm;           // 16896
    float* part  = hl + 16896;   // 1552
    float* logit = part + 1552;  // 104
    float* alpha = logit + 104;  // 104
    int* cstart = (int*)(alpha + 104);
    int* ceid   = cstart + NN + 1;
    int* csrc   = ceid + EE;
    int* cdst   = csrc + EE;

    const float4* srcl = (const float4*)(d_hl + (long)t * NC2);
    for (int i = tid; i < NC2 / 4; i += 512)
        ((float4*)hl)[i] = srcl[i];
    if (tid < NN + 1) cstart[tid] = d_csr_start[tid];
    if (tid < EE) { ceid[tid] = d_csr_eid[tid]; csrc[tid] = d_src[tid]; cdst[tid] = d_dst[tid]; }
    float attc = att2[tid];
    float b = bias2[tid];
    const float* hrg = d_hr + (long)t * NC2;
    __syncthreads();

    int lane = tid & 31, warp = tid >> 5;
#pragma unroll 4
    for (int e = 0; e < EE; e++) {
        int s = csrc[e], d = cdst[e];
        float v = hl[s * C2 + tid] + __ldg(hrg + d * C2 + tid) + __ldg(&d_ep2[e * C2 + tid]);
        v = fmaxf(v, 0.2f * v);
        v *= attc;
        v += __shfl_xor_sync(0xffffffffu, v, 16);
        v += __shfl_xor_sync(0xffffffffu, v, 8);
        v += __shfl_xor_sync(0xffffffffu, v, 4);
        v += __shfl_xor_sync(0xffffffffu, v, 2);
        v += __shfl_xor_sync(0xffffffffu, v, 1);
        if (lane == 0) part[e * 16 + warp] = v;
    }
    __syncthreads();
    if (tid < EE) {
        float s = 0.0f;
        for (int w = 0; w < 16; w++) s += part[tid * 16 + w];
        logit[tid] = s;
    }
    __syncthreads();
    if (tid < NN) {
        int s0 = cstart[tid], s1 = cstart[tid + 1];
        float m = -INFINITY;
        for (int p = s0; p < s1; p++) m = fmaxf(m, logit[ceid[p]]);
        float den = 0.0f;
        for (int p = s0; p < s1; p++) {
            float ex = expf(logit[ceid[p]] - m);
            den += ex;
            alpha[ceid[p]] = ex;
        }
        float inv = 1.0f / (den + 1e-16f);
        for (int p = s0; p < s1; p++) alpha[ceid[p]] *= inv;
    }
    __syncthreads();
    for (int n = 0; n < NN; n++) {
        int s0 = cstart[n], s1 = cstart[n + 1];
        float acc = 0.0f;
        for (int p = s0; p < s1; p++) {
            int e = ceid[p];
            acc = fmaf(alpha[e], hl[csrc[e] * C2 + tid], acc);
        }
        float o = acc + b;
        o = o > 0.0f ? o : expm1f(o);
        d_seq[((long)n * TT + t) * C2 + tid] = o;
    }
}

// ---------- K4a: init xpre1 with biases ----------
__global__ __launch_bounds__(512) void k_xpre_init() {
    d_xpre1[blockIdx.x * Z1 + threadIdx.x] = d_lb1[threadIdx.x];
}

// ---------- K4: split-K NT GEMM  xpre1 += seq @ l1_wih^T, FFMA2 ----------
__global__ __launch_bounds__(256) void k_gemm2(const float* __restrict__ Bw) {
    int bx = blockIdx.x, by = blockIdx.y, bz = blockIdx.z;
    __shared__ __align__(16) float As[16][64];
    __shared__ __align__(16) float Bs[16][64];
    int tid = threadIdx.x;
    int tx = tid & 15, ty = tid >> 4;
    ull acc2[4][2];
#pragma unroll
    for (int i = 0; i < 4; i++) { acc2[i][0] = 0ull; acc2[i][1] = 0ull; }
    int lrow = tid >> 2, lc4 = (tid & 3) * 4;
    long abase = (long)(by * 64 + lrow) * NC2 + lc4;
    long bbase = (long)(bx * 64 + lrow) * NC2 + lc4;
    int k0 = 2112 * bz, kend = k0 + 2112;
    for (; k0 < kend; k0 += 16) {
        float4 av = *(const float4*)(d_seq + abase + k0);
        float4 bv = *(const float4*)(Bw + bbase + k0);
        As[lc4 + 0][lrow] = av.x; As[lc4 + 1][lrow] = av.y;
        As[lc4 + 2][lrow] = av.z; As[lc4 + 3][lrow] = av.w;
        Bs[lc4 + 0][lrow] = bv.x; Bs[lc4 + 1][lrow] = bv.y;
        Bs[lc4 + 2][lrow] = bv.z; Bs[lc4 + 3][lrow] = bv.w;
        __syncthreads();
#pragma unroll
        for (int kk = 0; kk < 16; kk++) {
            float a[4];
            *(float4*)a = *(float4*)&As[kk][ty * 4];
            ulonglong2 b0 = *(const ulonglong2*)&Bs[kk][tx * 4];
#pragma unroll
            for (int i = 0; i < 4; i++) {
                ull ap = pk2(a[i], a[i]);
                acc2[i][0] = ffma2(ap, b0.x, acc2[i][0]);
                acc2[i][1] = ffma2(ap, b0.y, acc2[i][1]);
            }
        }
        __syncthreads();
    }
#pragma unroll
    for (int i = 0; i < 4; i++) {
        float2 f0 = upk2(acc2[i][0]), f1 = upk2(acc2[i][1]);
        float* dst = &d_xpre1[(by * 64 + ty * 4 + i) * Z1 + bx * 64 + tx * 4];
        atomicAdd(dst + 0, f0.x);
        atomicAdd(dst + 1, f0.y);
        atomicAdd(dst + 2, f1.x);
        atomicAdd(dst + 3, f1.y);
    }
}

// ---------- K5: LSTM1 recurrence (single block, 512 threads), FFMA2 ----------
__global__ __launch_bounds__(512, 1) void k_lstm1(const float* __restrict__ whh) {
    int j = threadIdx.x;
    extern __shared__ float sm[];
    float* sw  = sm;                         // WSM/4 chunks * 512 * 4 floats
    float* hsm = sw + (WSM / 4) * 512 * 4;   // 128
    float* zsm = hsm + 128;                  // 512

    ull wd[WREG / 2];
#pragma unroll
    for (int q4 = 0; q4 < WREG / 4; q4++) {
        ulonglong2 v = *(const ulonglong2*)(whh + j * HID1 + 4 * q4);
        wd[2 * q4] = v.x; wd[2 * q4 + 1] = v.y;
    }
#pragma unroll
    for (int kk4 = 0; kk4 < WSM / 4; kk4++)
        ((float4*)sw)[kk4 * 512 + j] = *(const float4*)(whh + j * HID1 + WREG + kk4 * 4);
    if (j < HID1) hsm[j] = 0.0f;
    float c = 0.0f;
    __syncthreads();

    const ulonglong2* h2 = (const ulonglong2*)hsm;   // pairs of h
    const ulonglong2* sw2 = (const ulonglong2*)sw;
    float xv = d_xpre1[j];
    for (int t = 0; t < TT; t++) {
        ull pa = pk2(xv, 0.0f), pb = 0ull;
#pragma unroll
        for (int q4 = 0; q4 < WREG / 4; q4++) {
            ulonglong2 hv = h2[q4];
            pa = ffma2(wd[2 * q4],     hv.x, pa);
            pb = ffma2(wd[2 * q4 + 1], hv.y, pb);
        }
#pragma unroll
        for (int kk4 = 0; kk4 < WSM / 4; kk4++) {
            ulonglong2 w = sw2[kk4 * 512 + j];
            ulonglong2 hv = h2[WREG / 4 + kk4];
            pa = ffma2(w.x, hv.x, pa);
            pb = ffma2(w.y, hv.y, pb);
        }
        float2 fa = upk2(pa), fb = upk2(pb);
        zsm[j] = (fa.x + fb.x) + (fa.y + fb.y);
        if (t + 1 < TT) xv = d_xpre1[(t + 1) * Z1 + j];
        __syncthreads();
        if (j < HID1) {
            float zi = zsm[j], zf = zsm[HID1 + j], zg = zsm[2 * HID1 + j], zo = zsm[3 * HID1 + j];
            c = sigm(zf) * c + sigm(zi) * tanhf(zg);
            float h = sigm(zo) * tanhf(c);
            hsm[j] = h;
            d_hs1[t * HID1 + j] = h;
        }
        __syncthreads();
    }
}

// ---------- K6: xpre2 = hs1 @ l2_wih^T + lb2 ----------
__global__ __launch_bounds__(256) void k_xpre2(const float* __restrict__ wih2) {
    int t = blockIdx.x;
    int tid = threadIdx.x;
    __shared__ __align__(16) float h[HID1];
    if (tid < HID1) h[tid] = d_hs1[t * HID1 + tid];
    __syncthreads();
    const ulonglong2* w2 = (const ulonglong2*)(wih2 + tid * HID1);
    const ulonglong2* h2 = (const ulonglong2*)h;
    ull pa = 0ull, pb = 0ull;
#pragma unroll
    for (int q4 = 0; q4 < HID1 / 4; q4++) {
        ulonglong2 w = w2[q4], hv = h2[q4];
        pa = ffma2(w.x, hv.x, pa);
        pb = ffma2(w.y, hv.y, pb);
    }
    float2 fa = upk2(pa), fb = upk2(pb);
    d_xpre2[t * Z2 + tid] = (fa.x + fb.x) + (fa.y + fb.y) + d_lb2[tid];
}

// ---------- K7: LSTM2 recurrence + FC, FFMA2 ----------
__global__ __launch_bounds__(256, 1) void k_lstm2(const float* __restrict__ whh2,
                                                  const float* __restrict__ fcw,
                                                  const float* __restrict__ fcb,
                                                  float* __restrict__ out) {
    int j = threadIdx.x;
    __shared__ __align__(16) float hsm[HID2];
    __shared__ float zsm[Z2];
    ull wd[HID2 / 2];
#pragma unroll
    for (int q4 = 0; q4 < HID2 / 4; q4++) {
        ulonglong2 v = *(const ulonglong2*)(whh2 + j * HID2 + 4 * q4);
        wd[2 * q4] = v.x; wd[2 * q4 + 1] = v.y;
    }
    if (j < HID2) hsm[j] = 0.0f;
    float c = 0.0f;
    __syncthreads();
    const ulonglong2* h2 = (const ulonglong2*)hsm;
    float xv = d_xpre2[j];
    for (int t = 0; t < TT; t++) {
        ull pa = pk2(xv, 0.0f), pb = 0ull;
#pragma unroll
        for (int q4 = 0; q4 < HID2 / 4; q4++) {
            ulonglong2 hv = h2[q4];
            pa = ffma2(wd[2 * q4],     hv.x, pa);
            pb = ffma2(wd[2 * q4 + 1], hv.y, pb);
        }
        float2 fa = upk2(pa), fb = upk2(pb);
        zsm[j] = (fa.x + fb.x) + (fa.y + fb.y);
        if (t + 1 < TT) xv = d_xpre2[(t + 1) * Z2 + j];
        __syncthreads();
        if (j < HID2) {
            float zi = zsm[j], zf = zsm[HID2 + j], zg = zsm[2 * HID2 + j], zo = zsm[3 * HID2 + j];
            c = sigm(zf) * c + sigm(zi) * tanhf(zg);
            hsm[j] = sigm(zo) * tanhf(c);
        }
        __syncthreads();
    }
    if (j < 4) {
        float acc = fcb[j];
        for (int k = 0; k < HID2; k++) acc = fmaf(fcw[j * HID2 + k], hsm[k], acc);
        out[j] = acc;
    }
}

extern "C" void kernel_launch(void* const* d_in, const int* in_sizes, int n_in,
                              void* d_out, int out_size) {
    const float* x      = (const float*)d_in[0];
    const int*   ei     = (const int*)d_in[1];
    const float* ea     = (const float*)d_in[2];
    const float* g1_wl  = (const float*)d_in[3];
    const float* g1_wr  = (const float*)d_in[4];
    const float* g1_we  = (const float*)d_in[5];
    const float* g1_att = (const float*)d_in[6];
    const float* g1_b   = (const float*)d_in[7];
    const float* g2_wl  = (const float*)d_in[8];
    const float* g2_wr  = (const float*)d_in[9];
    const float* g2_we  = (const float*)d_in[10];
    const float* g2_att = (const float*)d_in[11];
    const float* g2_b   = (const float*)d_in[12];
    const float* l1_wih = (const float*)d_in[13];
    const float* l1_whh = (const float*)d_in[14];
    const float* l1_bih = (const float*)d_in[15];
    const float* l1_bhh = (const float*)d_in[16];
    const float* l2_wih = (const float*)d_in[17];
    const float* l2_whh = (const float*)d_in[18];
    const float* l2_bih = (const float*)d_in[19];
    const float* l2_bhh = (const float*)d_in[20];
    const float* fc_w   = (const float*)d_in[21];
    const float* fc_b   = (const float*)d_in[22];
    float* out = (float*)d_out;

    const int SMEM_GAT1  = (16896 + 1552 + 776 + 776 + 68) * 4 + 325 * 4;
    const int SMEM_GAT2  = (16896 + 1552 + 104 + 104) * 4 + 325 * 4;
    const int SMEM_LSTM1 = ((WSM / 4) * 512 * 4 + 128 + 512) * 4;
    cudaFuncSetAttribute(k_gat1, cudaFuncAttributeMaxDynamicSharedMemorySize, SMEM_GAT1);
    cudaFuncSetAttribute(k_gat2, cudaFuncAttributeMaxDynamicSharedMemorySize, SMEM_GAT2);
    cudaFuncSetAttribute(k_lstm1, cudaFuncAttributeMaxDynamicSharedMemorySize, SMEM_LSTM1);

    k_setup<<<1, 512>>>(ei, ea, g1_we, g2_we, l1_bih, l1_bhh, l2_bih, l2_bhh);
    k_gat1<<<TT, 512, SMEM_GAT1>>>(x, g1_wl, g1_wr, g1_att, g1_b);
    k_gemm1<<<dim3(8, 264), 256>>>(g2_wl, g2_wr);
    k_gat2<<<TT, 512, SMEM_GAT2>>>(g2_att, g2_b);
    k_xpre_init<<<TT, Z1>>>();
    k_gemm2<<<dim3(8, 16, 8), 256>>>(l1_wih);
    k_lstm1<<<1, 512, SMEM_LSTM1>>>(l1_whh);
    k_xpre2<<<TT, 256>>>(l2_wih);
    k_lstm2<<<1, 256>>>(l2_whh, fc_w, fc_b, out);
}

// round 5
// speedup vs baseline: 1.2195x; 1.0999x over previous
#include <cuda_runtime.h>
#include <math.h>

#define NN 33
#define TT 1024
#define EE 97
#define H1 8
#define HC 512
#define C2 512
#define HID1 128
#define Z1 512
#define NC2 16896
#define HID2 64
#define Z2 256
#define WREG 96
#define WSM  32   // WREG + WSM == HID1

typedef unsigned long long ull;

__device__ float d_ep1[EE * HC];
__device__ float d_ep2[EE * C2];
__device__ int   d_csr_start[NN + 1];
__device__ int   d_csr_eid[EE];
__device__ int   d_src[EE];
__device__ int   d_dst[EE];
__device__ float d_h1[TT * NN * HC];
__device__ float d_hl[TT * NN * C2];
__device__ float d_hr[TT * NN * C2];
__device__ float d_seq[NN * TT * C2];
__device__ float d_xpre1[TT * Z1];
__device__ float d_hs1[TT * HID1];
__device__ float d_xpre2[TT * Z2];
__device__ float d_lb1[Z1];
__device__ float d_lb2[Z2];

__device__ __forceinline__ float sigm(float x) { return 1.0f / (1.0f + expf(-x)); }

__device__ __forceinline__ ull ffma2(ull a, ull b, ull c) {
    ull d;
    asm("fma.rn.f32x2 %0, %1, %2, %3;" : "=l"(d) : "l"(a), "l"(b), "l"(c));
    return d;
}
__device__ __forceinline__ ull pk2(float lo, float hi) {
    ull r;
    asm("mov.b64 %0, {%1, %2};" : "=l"(r) : "f"(lo), "f"(hi));
    return r;
}
__device__ __forceinline__ float2 upk2(ull v) {
    float2 f;
    asm("mov.b64 {%0, %1}, %2;" : "=f"(f.x), "=f"(f.y) : "l"(v));
    return f;
}

// ---------- K0: setup ----------
__global__ __launch_bounds__(512) void k_setup(const int* __restrict__ ei, const float* __restrict__ ea,
                        const float* __restrict__ g1_we, const float* __restrict__ g2_we,
                        const float* __restrict__ b1i, const float* __restrict__ b1h,
                        const float* __restrict__ b2i, const float* __restrict__ b2h) {
    __shared__ int cnt[NN + 1];
    __shared__ int pos[NN];
    int tid = threadIdx.x;
    if (tid == 0) {
        for (int n = 0; n <= NN; n++) cnt[n] = 0;
        for (int e = 0; e < EE; e++) {
            d_src[e] = ei[e];
            d_dst[e] = ei[EE + e];
            cnt[ei[EE + e] + 1]++;
        }
        for (int n = 0; n < NN; n++) cnt[n + 1] += cnt[n];
        for (int n = 0; n <= NN; n++) d_csr_start[n] = cnt[n];
        for (int n = 0; n < NN; n++) pos[n] = cnt[n];
        for (int e = 0; e < EE; e++) d_csr_eid[pos[ei[EE + e]]++] = e;
    }
    for (int e = 0; e < EE; e++) {
        float a0 = ea[e * 3], a1 = ea[e * 3 + 1], a2 = ea[e * 3 + 2];
        d_ep1[e * HC + tid] = a0 * g1_we[tid] + a1 * g1_we[HC + tid] + a2 * g1_we[2 * HC + tid];
        d_ep2[e * C2 + tid] = a0 * g2_we[tid] + a1 * g2_we[C2 + tid] + a2 * g2_we[2 * C2 + tid];
    }
    d_lb1[tid] = b1i[tid] + b1h[tid];
    if (tid < Z2) d_lb2[tid] = b2i[tid] + b2h[tid];
}

// ---------- K1: GAT1 ----------
__global__ __launch_bounds__(512) void k_gat1(const float* __restrict__ x,
                                              const float* __restrict__ wl,
                                              const float* __restrict__ wr,
                                              const float* __restrict__ att,
                                              const float* __restrict__ bias) {
    int t = blockIdx.x;
    int tid = threadIdx.x;
    extern __shared__ float sm[];
    float* xl    = sm;            // 16896
    float* part  = xl + 16896;    // 97*16
    float* logit = part + 1552;   // 97*8
    float* alpha = logit + 776;   // 97*8
    float* sx    = alpha + 776;   // 68
    int* cstart = (int*)(sx + 68);
    int* ceid   = cstart + NN + 1;
    int* csrc   = ceid + EE;
    int* cdst   = csrc + EE;

    if (tid < 2 * NN) sx[tid] = x[t * (2 * NN) + tid];
    if (tid < NN + 1) cstart[tid] = d_csr_start[tid];
    if (tid < EE) { ceid[tid] = d_csr_eid[tid]; csrc[tid] = d_src[tid]; cdst[tid] = d_dst[tid]; }
    float wl0 = wl[tid], wl1 = wl[HC + tid];
    float wr0 = wr[tid], wr1 = wr[HC + tid];
    float attc = att[tid];
    __syncthreads();

    for (int n = 0; n < NN; n++)
        xl[n * HC + tid] = fmaf(sx[2 * n], wl0, sx[2 * n + 1] * wl1);
    __syncthreads();

    int lane = tid & 31, warp = tid >> 5;
#pragma unroll 4
    for (int e = 0; e < EE; e++) {
        int s = csrc[e], d = cdst[e];
        float xr = fmaf(sx[2 * d], wr0, sx[2 * d + 1] * wr1);
        float v = xl[s * HC + tid] + xr + d_ep1[e * HC + tid];
        v = fmaxf(v, 0.2f * v);
        v *= attc;
        v += __shfl_xor_sync(0xffffffffu, v, 16);
        v += __shfl_xor_sync(0xffffffffu, v, 8);
        v += __shfl_xor_sync(0xffffffffu, v, 4);
        v += __shfl_xor_sync(0xffffffffu, v, 2);
        v += __shfl_xor_sync(0xffffffffu, v, 1);
        if (lane == 0) part[e * 16 + warp] = v;
    }
    __syncthreads();
    for (int idx = tid; idx < EE * H1; idx += 512) {
        int e = idx >> 3, h = idx & 7;
        logit[idx] = part[e * 16 + 2 * h] + part[e * 16 + 2 * h + 1];
    }
    __syncthreads();
    for (int idx = tid; idx < NN * H1; idx += 512) {
        int n = idx >> 3, h = idx & 7;
        int s0 = cstart[n], s1 = cstart[n + 1];
        float m = -INFINITY;
        for (int p = s0; p < s1; p++) m = fmaxf(m, logit[ceid[p] * 8 + h]);
        float den = 0.0f;
        for (int p = s0; p < s1; p++) {
            float ex = expf(logit[ceid[p] * 8 + h] - m);
            den += ex;
            alpha[ceid[p] * 8 + h] = ex;
        }
        float inv = 1.0f / (den + 1e-16f);
        for (int p = s0; p < s1; p++) alpha[ceid[p] * 8 + h] *= inv;
    }
    __syncthreads();
    int h = tid >> 6;
    float b = bias[tid];
    for (int n = 0; n < NN; n++) {
        int s0 = cstart[n], s1 = cstart[n + 1];
        float acc = 0.0f;
        for (int p = s0; p < s1; p++) {
            int e = ceid[p];
            acc = fmaf(alpha[e * 8 + h], xl[csrc[e] * HC + tid], acc);
        }
        float o = acc + b;
        o = o > 0.0f ? o : expm1f(o);
        d_h1[(t * NN + n) * HC + tid] = o;
    }
}

// ---------- K2: GEMM1 with register prefetch ----------
__global__ __launch_bounds__(256) void k_gemm1(const float* __restrict__ Bwl,
                                               const float* __restrict__ Bwr) {
    int n0 = blockIdx.x * 128;
    int by = blockIdx.y;
    const float* A = d_h1;
    const float* B = (n0 < 512) ? (Bwl + n0) : (Bwr + (n0 - 512));
    float*       C = (n0 < 512) ? (d_hl + n0) : (d_hr + (n0 - 512));
    __shared__ __align__(16) float As[8][128];
    __shared__ __align__(16) float Bs[8][128];
    int tid = threadIdx.x;
    int tx = tid & 15, ty = tid >> 4;
    ull acc2[8][4];
#pragma unroll
    for (int i = 0; i < 8; i++)
#pragma unroll
        for (int j = 0; j < 4; j++) acc2[i][j] = 0ull;
    int arow = tid >> 1, acol = (tid & 1) * 4;
    int brow = tid >> 5, bcol = (tid & 31) * 4;
    long abase = (long)(by * 128 + arow) * 512 + acol;

    float4 av = *(const float4*)(A + abase);
    float4 bv = *(const float4*)(B + brow * 512 + bcol);
    for (int k0 = 0; k0 < 512; k0 += 8) {
        As[acol + 0][arow] = av.x; As[acol + 1][arow] = av.y;
        As[acol + 2][arow] = av.z; As[acol + 3][arow] = av.w;
        *(float4*)&Bs[brow][bcol] = bv;
        __syncthreads();
        if (k0 + 8 < 512) {
            av = *(const float4*)(A + abase + k0 + 8);
            bv = *(const float4*)(B + (k0 + 8 + brow) * 512 + bcol);
        }
#pragma unroll
        for (int kk = 0; kk < 8; kk++) {
            float a[8];
            *(float4*)(a)     = *(float4*)&As[kk][ty * 8];
            *(float4*)(a + 4) = *(float4*)&As[kk][ty * 8 + 4];
            ulonglong2 b0 = *(const ulonglong2*)&Bs[kk][tx * 8];
            ulonglong2 b1 = *(const ulonglong2*)&Bs[kk][tx * 8 + 4];
#pragma unroll
            for (int i = 0; i < 8; i++) {
                ull ap = pk2(a[i], a[i]);
                acc2[i][0] = ffma2(ap, b0.x, acc2[i][0]);
                acc2[i][1] = ffma2(ap, b0.y, acc2[i][1]);
                acc2[i][2] = ffma2(ap, b1.x, acc2[i][2]);
                acc2[i][3] = ffma2(ap, b1.y, acc2[i][3]);
            }
        }
        __syncthreads();
    }
#pragma unroll
    for (int i = 0; i < 8; i++) {
        long m = (long)(by * 128 + ty * 8 + i) * 512 + tx * 8;
        float2 f0 = upk2(acc2[i][0]), f1 = upk2(acc2[i][1]);
        float2 f2 = upk2(acc2[i][2]), f3 = upk2(acc2[i][3]);
        *(float4*)(C + m)     = make_float4(f0.x, f0.y, f1.x, f1.y);
        *(float4*)(C + m + 4) = make_float4(f2.x, f2.y, f3.x, f3.y);
    }
}

// ---------- K3: GAT2 ----------
__global__ __launch_bounds__(512) void k_gat2(const float* __restrict__ att2,
                                              const float* __restrict__ bias2) {
    int t = blockIdx.x;
    int tid = threadIdx.x;
    extern __shared__ float sm[];
    float* hl    = sm;           // 16896
    float* part  = hl + 16896;   // 1552
    float* logit = part + 1552;  // 104
    float* alpha = logit + 104;  // 104
    int* cstart = (int*)(alpha + 104);
    int* ceid   = cstart + NN + 1;
    int* csrc   = ceid + EE;
    int* cdst   = csrc + EE;

    const float4* srcl = (const float4*)(d_hl + (long)t * NC2);
    for (int i = tid; i < NC2 / 4; i += 512)
        ((float4*)hl)[i] = srcl[i];
    if (tid < NN + 1) cstart[tid] = d_csr_start[tid];
    if (tid < EE) { ceid[tid] = d_csr_eid[tid]; csrc[tid] = d_src[tid]; cdst[tid] = d_dst[tid]; }
    float attc = att2[tid];
    float b = bias2[tid];
    const float* hrg = d_hr + (long)t * NC2;
    __syncthreads();

    int lane = tid & 31, warp = tid >> 5;
#pragma unroll 4
    for (int e = 0; e < EE; e++) {
        int s = csrc[e], d = cdst[e];
        float v = hl[s * C2 + tid] + __ldg(hrg + d * C2 + tid) + __ldg(&d_ep2[e * C2 + tid]);
        v = fmaxf(v, 0.2f * v);
        v *= attc;
        v += __shfl_xor_sync(0xffffffffu, v, 16);
        v += __shfl_xor_sync(0xffffffffu, v, 8);
        v += __shfl_xor_sync(0xffffffffu, v, 4);
        v += __shfl_xor_sync(0xffffffffu, v, 2);
        v += __shfl_xor_sync(0xffffffffu, v, 1);
        if (lane == 0) part[e * 16 + warp] = v;
    }
    __syncthreads();
    if (tid < EE) {
        float s = 0.0f;
        for (int w = 0; w < 16; w++) s += part[tid * 16 + w];
        logit[tid] = s;
    }
    __syncthreads();
    if (tid < NN) {
        int s0 = cstart[tid], s1 = cstart[tid + 1];
        float m = -INFINITY;
        for (int p = s0; p < s1; p++) m = fmaxf(m, logit[ceid[p]]);
        float den = 0.0f;
        for (int p = s0; p < s1; p++) {
            float ex = expf(logit[ceid[p]] - m);
            den += ex;
            alpha[ceid[p]] = ex;
        }
        float inv = 1.0f / (den + 1e-16f);
        for (int p = s0; p < s1; p++) alpha[ceid[p]] *= inv;
    }
    __syncthreads();
    for (int n = 0; n < NN; n++) {
        int s0 = cstart[n], s1 = cstart[n + 1];
        float acc = 0.0f;
        for (int p = s0; p < s1; p++) {
            int e = ceid[p];
            acc = fmaf(alpha[e], hl[csrc[e] * C2 + tid], acc);
        }
        float o = acc + b;
        o = o > 0.0f ? o : expm1f(o);
        d_seq[((long)n * TT + t) * C2 + tid] = o;
    }
}

// ---------- K4a ----------
__global__ __launch_bounds__(512) void k_xpre_init() {
    d_xpre1[blockIdx.x * Z1 + threadIdx.x] = d_lb1[threadIdx.x];
}

// ---------- K4: split-K GEMM with register prefetch ----------
__global__ __launch_bounds__(256) void k_gemm2(const float* __restrict__ Bw) {
    int bx = blockIdx.x, by = blockIdx.y, bz = blockIdx.z;
    __shared__ __align__(16) float As[16][64];
    __shared__ __align__(16) float Bs[16][64];
    int tid = threadIdx.x;
    int tx = tid & 15, ty = tid >> 4;
    ull acc2[4][2];
#pragma unroll
    for (int i = 0; i < 4; i++) { acc2[i][0] = 0ull; acc2[i][1] = 0ull; }
    int lrow = tid >> 2, lc4 = (tid & 3) * 4;
    long abase = (long)(by * 64 + lrow) * NC2 + lc4;
    long bbase = (long)(bx * 64 + lrow) * NC2 + lc4;
    int kbeg = 2112 * bz, kend = kbeg + 2112;
    float4 av = *(const float4*)(d_seq + abase + kbeg);
    float4 bv = *(const float4*)(Bw + bbase + kbeg);
    for (int k0 = kbeg; k0 < kend; k0 += 16) {
        As[lc4 + 0][lrow] = av.x; As[lc4 + 1][lrow] = av.y;
        As[lc4 + 2][lrow] = av.z; As[lc4 + 3][lrow] = av.w;
        Bs[lc4 + 0][lrow] = bv.x; Bs[lc4 + 1][lrow] = bv.y;
        Bs[lc4 + 2][lrow] = bv.z; Bs[lc4 + 3][lrow] = bv.w;
        __syncthreads();
        if (k0 + 16 < kend) {
            av = *(const float4*)(d_seq + abase + k0 + 16);
            bv = *(const float4*)(Bw + bbase + k0 + 16);
        }
#pragma unroll
        for (int kk = 0; kk < 16; kk++) {
            float a[4];
            *(float4*)a = *(float4*)&As[kk][ty * 4];
            ulonglong2 b0 = *(const ulonglong2*)&Bs[kk][tx * 4];
#pragma unroll
            for (int i = 0; i < 4; i++) {
                ull ap = pk2(a[i], a[i]);
                acc2[i][0] = ffma2(ap, b0.x, acc2[i][0]);
                acc2[i][1] = ffma2(ap, b0.y, acc2[i][1]);
            }
        }
        __syncthreads();
    }
#pragma unroll
    for (int i = 0; i < 4; i++) {
        float2 f0 = upk2(acc2[i][0]), f1 = upk2(acc2[i][1]);
        float* dst = &d_xpre1[(by * 64 + ty * 4 + i) * Z1 + bx * 64 + tx * 4];
        atomicAdd(dst + 0, f0.x);
        atomicAdd(dst + 1, f0.y);
        atomicAdd(dst + 2, f1.x);
        atomicAdd(dst + 3, f1.y);
    }
}

// ---------- K5: LSTM1 (512 thr; 96 reg weights + 32 smem; activation-spread) ----------
__global__ __launch_bounds__(512, 1) void k_lstm1(const float* __restrict__ whh) {
    int j = threadIdx.x;
    extern __shared__ float sm[];
    float* sw  = sm;                         // (WSM/4)*512 float4
    float* hsm = sw + (WSM / 4) * 512 * 4;   // 128
    float* zsm = hsm + 128;                  // 512 (activated gates)

    ull wd[WREG / 2];
#pragma unroll
    for (int q4 = 0; q4 < WREG / 4; q4++) {
        ulonglong2 v = *(const ulonglong2*)(whh + j * HID1 + 4 * q4);
        wd[2 * q4] = v.x; wd[2 * q4 + 1] = v.y;
    }
#pragma unroll
    for (int kk4 = 0; kk4 < WSM / 4; kk4++)
        ((float4*)sw)[kk4 * 512 + j] = *(const float4*)(whh + j * HID1 + WREG + kk4 * 4);
    if (j < HID1) hsm[j] = 0.0f;
    float c = 0.0f;
    int gate = j >> 7;   // 0:i 1:f 2:g 3:o
    __syncthreads();

    const ulonglong2* h2 = (const ulonglong2*)hsm;
    const ulonglong2* sw2 = (const ulonglong2*)sw;
    float xv = d_xpre1[j];
    for (int t = 0; t < TT; t++) {
        ull pa = pk2(xv, 0.0f), pb = 0ull;
#pragma unroll
        for (int q4 = 0; q4 < WREG / 4; q4++) {
            ulonglong2 hv = h2[q4];
            pa = ffma2(wd[2 * q4],     hv.x, pa);
            pb = ffma2(wd[2 * q4 + 1], hv.y, pb);
        }
#pragma unroll
        for (int kk4 = 0; kk4 < WSM / 4; kk4++) {
            ulonglong2 w = sw2[kk4 * 512 + j];
            ulonglong2 hv = h2[WREG / 4 + kk4];
            pa = ffma2(w.x, hv.x, pa);
            pb = ffma2(w.y, hv.y, pb);
        }
        float2 fa = upk2(pa), fb = upk2(pb);
        float z = (fa.x + fb.x) + (fa.y + fb.y);
        zsm[j] = (gate == 2) ? tanhf(z) : sigm(z);   // pre-activate
        if (t + 1 < TT) xv = d_xpre1[(t + 1) * Z1 + j];
        __syncthreads();
        if (j < HID1) {
            float ai = zsm[j], af = zsm[HID1 + j], ag = zsm[2 * HID1 + j], ao = zsm[3 * HID1 + j];
            c = af * c + ai * ag;
            float h = ao * tanhf(c);
            hsm[j] = h;
            d_hs1[t * HID1 + j] = h;
        }
        __syncthreads();
    }
}

// ---------- K6: xpre2 ----------
__global__ __launch_bounds__(256) void k_xpre2(const float* __restrict__ wih2) {
    int t = blockIdx.x;
    int tid = threadIdx.x;
    __shared__ __align__(16) float h[HID1];
    if (tid < HID1) h[tid] = d_hs1[t * HID1 + tid];
    __syncthreads();
    const ulonglong2* w2 = (const ulonglong2*)(wih2 + tid * HID1);
    const ulonglong2* h2 = (const ulonglong2*)h;
    ull pa = 0ull, pb = 0ull;
#pragma unroll
    for (int q4 = 0; q4 < HID1 / 4; q4++) {
        ulonglong2 w = w2[q4], hv = h2[q4];
        pa = ffma2(w.x, hv.x, pa);
        pb = ffma2(w.y, hv.y, pb);
    }
    float2 fa = upk2(pa), fb = upk2(pb);
    d_xpre2[t * Z2 + tid] = (fa.x + fb.x) + (fa.y + fb.y) + d_lb2[tid];
}

// ---------- K7: LSTM2 + FC (activation-spread) ----------
__global__ __launch_bounds__(256, 1) void k_lstm2(const float* __restrict__ whh2,
                                                  const float* __restrict__ fcw,
                                                  const float* __restrict__ fcb,
                                                  float* __restrict__ out) {
    int j = threadIdx.x;
    __shared__ __align__(16) float hsm[HID2];
    __shared__ float zsm[Z2];
    ull wd[HID2 / 2];
#pragma unroll
    for (int q4 = 0; q4 < HID2 / 4; q4++) {
        ulonglong2 v = *(const ulonglong2*)(whh2 + j * HID2 + 4 * q4);
        wd[2 * q4] = v.x; wd[2 * q4 + 1] = v.y;
    }
    if (j < HID2) hsm[j] = 0.0f;
    float c = 0.0f;
    int gate = j >> 6;
    __syncthreads();
    const ulonglong2* h2 = (const ulonglong2*)hsm;
    float xv = d_xpre2[j];
    for (int t = 0; t < TT; t++) {
        ull pa = pk2(xv, 0.0f), pb = 0ull;
#pragma unroll
        for (int q4 = 0; q4 < HID2 / 4; q4++) {
            ulonglong2 hv = h2[q4];
            pa = ffma2(wd[2 * q4],     hv.x, pa);
            pb = ffma2(wd[2 * q4 + 1], hv.y, pb);
        }
        float2 fa = upk2(pa), fb = upk2(pb);
        float z = (fa.x + fb.x) + (fa.y + fb.y);
        zsm[j] = (gate == 2) ? tanhf(z) : sigm(z);
        if (t + 1 < TT) xv = d_xpre2[(t + 1) * Z2 + j];
        __syncthreads();
        if (j < HID2) {
            float ai = zsm[j], af = zsm[HID2 + j], ag = zsm[2 * HID2 + j], ao = zsm[3 * HID2 + j];
            c = af * c + ai * ag;
            hsm[j] = ao * tanhf(c);
        }
        __syncthreads();
    }
    if (j < 4) {
        float acc = fcb[j];
        for (int k = 0; k < HID2; k++) acc = fmaf(fcw[j * HID2 + k], hsm[k], acc);
        out[j] = acc;
    }
}

extern "C" void kernel_launch(void* const* d_in, const int* in_sizes, int n_in,
                              void* d_out, int out_size) {
    const float* x      = (const float*)d_in[0];
    const int*   ei     = (const int*)d_in[1];
    const float* ea     = (const float*)d_in[2];
    const float* g1_wl  = (const float*)d_in[3];
    const float* g1_wr  = (const float*)d_in[4];
    const float* g1_we  = (const float*)d_in[5];
    const float* g1_att = (const float*)d_in[6];
    const float* g1_b   = (const float*)d_in[7];
    const float* g2_wl  = (const float*)d_in[8];
    const float* g2_wr  = (const float*)d_in[9];
    const float* g2_we  = (const float*)d_in[10];
    const float* g2_att = (const float*)d_in[11];
    const float* g2_b   = (const float*)d_in[12];
    const float* l1_wih = (const float*)d_in[13];
    const float* l1_whh = (const float*)d_in[14];
    const float* l1_bih = (const float*)d_in[15];
    const float* l1_bhh = (const float*)d_in[16];
    const float* l2_wih = (const float*)d_in[17];
    const float* l2_whh = (const float*)d_in[18];
    const float* l2_bih = (const float*)d_in[19];
    const float* l2_bhh = (const float*)d_in[20];
    const float* fc_w   = (const float*)d_in[21];
    const float* fc_b   = (const float*)d_in[22];
    float* out = (float*)d_out;

    const int SMEM_GAT1  = (16896 + 1552 + 776 + 776 + 68) * 4 + 325 * 4;
    const int SMEM_GAT2  = (16896 + 1552 + 104 + 104) * 4 + 325 * 4;
    const int SMEM_LSTM1 = ((WSM / 4) * 512 * 4 + 128 + 512) * 4;
    cudaFuncSetAttribute(k_gat1, cudaFuncAttributeMaxDynamicSharedMemorySize, SMEM_GAT1);
    cudaFuncSetAttribute(k_gat2, cudaFuncAttributeMaxDynamicSharedMemorySize, SMEM_GAT2);
    cudaFuncSetAttribute(k_lstm1, cudaFuncAttributeMaxDynamicSharedMemorySize, SMEM_LSTM1);

    k_setup<<<1, 512>>>(ei, ea, g1_we, g2_we, l1_bih, l1_bhh, l2_bih, l2_bhh);
    k_gat1<<<TT, 512, SMEM_GAT1>>>(x, g1_wl, g1_wr, g1_att, g1_b);
    k_gemm1<<<dim3(8, 264), 256>>>(g2_wl, g2_wr);
    k_gat2<<<TT, 512, SMEM_GAT2>>>(g2_att, g2_b);
    k_xpre_init<<<TT, Z1>>>();
    k_gemm2<<<dim3(8, 16, 8), 256>>>(l1_wih);
    k_lstm1<<<1, 512, SMEM_LSTM1>>>(l1_whh);
    k_xpre2<<<TT, 256>>>(l2_wih);
    k_lstm2<<<1, 256>>>(l2_whh, fc_w, fc_b, out);
}